// round 15
// baseline (speedup 1.0000x reference)
#include <cuda_runtime.h>
#include <math.h>

#define Bq 8
#define Nn 1024
#define Ee 16384
#define ELCAP 192

typedef unsigned long long u64;

__device__ float g_dinv[Nn];
__device__ int   g_off[Nn + 1];
__device__ int   g_adj[Ee];

__device__ __forceinline__ u64 pk2(float x) {
    unsigned int xi = __float_as_uint(x);
    u64 r;
    asm("mov.b64 %0, {%1, %1};" : "=l"(r) : "r"(xi));
    return r;
}
__device__ __forceinline__ void fma2(u64& d, u64 a, u64 b) {
    asm("fma.rn.f32x2 %0, %1, %2, %3;" : "=l"(d) : "l"(a), "l"(b), "l"(d));
}
__device__ __forceinline__ float ftanh(float v) {
    float r;
    asm("tanh.approx.f32 %0, %1;" : "=f"(r) : "f"(v));
    return r;
}
__device__ __forceinline__ float2 tanh2(u64 a) {
    unsigned int lo, hi;
    asm("mov.b64 {%0, %1}, %2;" : "=r"(lo), "=r"(hi) : "l"(a));
    float2 r;
    r.x = ftanh(__uint_as_float(lo));
    r.y = ftanh(__uint_as_float(hi));
    return r;
}

// ---- one-CTA CSR build: deg->dinv, offsets, fill, per-node sort -------------
__global__ void k_prep(const int* __restrict__ ei) {
    __shared__ int sdeg[Nn];
    __shared__ int scur[Nn];
    const int tid = threadIdx.x;
    sdeg[tid] = 0;
    __syncthreads();
    const int* colp = ei + Ee;
    for (int e = tid; e < Ee; e += 1024) atomicAdd(&sdeg[colp[e]], 1);
    __syncthreads();
    const int d0 = sdeg[tid];
    g_dinv[tid] = rsqrtf((float)d0 + 1.0f);
    scur[tid] = d0;
    __syncthreads();
    for (int d = 1; d < Nn; d <<= 1) {
        int v = (tid >= d) ? scur[tid - d] : 0;
        __syncthreads();
        scur[tid] += v;
        __syncthreads();
    }
    const int incl = scur[tid];
    const int off = incl - d0;
    g_off[tid] = off;
    if (tid == Nn - 1) g_off[Nn] = incl;
    __syncthreads();
    scur[tid] = off;
    __syncthreads();
    for (int e = tid; e < Ee; e += 1024) {
        int c = colp[e];
        int pos = atomicAdd(&scur[c], 1);
        g_adj[pos] = ei[e];
    }
    __syncthreads();
    // per-node insertion sort -> deterministic fp sum order
    {
        int lo = off, hi = off + d0;
        for (int i = lo + 1; i < hi; i++) {
            int v = g_adj[i];
            int j = i - 1;
            while (j >= lo && g_adj[j] > v) { g_adj[j + 1] = g_adj[j]; j--; }
            g_adj[j + 1] = v;
        }
    }
}

#define XES 84
#define SMEM_FLOATS 11648

// grid = 2048, 256 threads. bid&1: 0 -> conv role (all 8 b), 1 -> spatial role.
__global__ void __launch_bounds__(256, 3)
k_work(const float* __restrict__ x, const int* __restrict__ ei,
       const float* __restrict__ w_t2, const float* __restrict__ b_t2,
       const float* __restrict__ w_t3, const float* __restrict__ b_t3,
       const float* __restrict__ w_t6, const float* __restrict__ b_t6,
       const float* __restrict__ w_t12, const float* __restrict__ b_t12,
       const float* __restrict__ w_gcn, const float* __restrict__ b_gcn,
       const float* __restrict__ w_slin, const float* __restrict__ b_slin,
       float* __restrict__ out) {
    __shared__ __align__(16) float sm[SMEM_FLOATS];
    const int bid = blockIdx.x;
    const int tid = threadIdx.x;
    const int cid = bid >> 1;
    const int role = bid & 1;

    if (role == 0) {
        // ==================== CONV ROLE (R14-validated, unchanged) ==========
        float* s_wA = sm;             // 3072
        float* s_wB = sm + 3072;      // 3072
        float* s_btc = sm + 6144;     // 64
        float* s_xe = sm + 6208;      // 16*84
        float* s_out = sm + 7552;     // 64*64 pair-swizzled

        const int n = cid;

        // Paired weight tables (validated layout):
        //  A (ks12): pairs p=0..5 -> taps (2p,2p+1)
        //  B: p0 br0 (sft 6,7); p1 br1 (5,6); p2 br1 (7, ZERO);
        //     p3 br2 (4,5); p4 br2 (6,7); p5 br2 (8,9)
        //  entry [(lo,oc0),(lo,oc1),(hi,oc0),(hi,oc1)] at ((c*6+p)*8+ocp)*4
        for (int i = tid; i < 6144; i += 256) {
            int il = (i < 3072) ? i : (i - 3072);
            int c = il / 192;
            int r = il - c * 192;
            int p = r >> 5;
            int ocp = (r >> 2) & 7;
            int qq = r & 3;
            int kh = qq >> 1;
            int oc = ocp * 2 + (qq & 1);
            float v;
            if (i < 3072) {
                v = w_t12[(oc * 16 + c) * 12 + 2 * p + kh];
            } else {
                if (p == 0)      v = w_t2[(oc * 16 + c) * 2 + kh];
                else if (p == 1) v = w_t3[(oc * 16 + c) * 3 + kh];
                else if (p == 2) v = kh ? 0.0f : w_t3[(oc * 16 + c) * 3 + 2];
                else             v = w_t6[(oc * 16 + c) * 6 + (p - 3) * 2 + kh];
            }
            sm[i] = v;
        }
        if (tid < 64) {
            s_btc[tid] = (tid < 16) ? b_t2[tid]
                       : (tid < 32) ? b_t3[tid - 16]
                       : (tid < 48) ? b_t6[tid - 32]
                                    : b_t12[tid - 48];
        }

        const int t = tid >> 2;            // loader mapping
        const int cq = (tid & 3) * 4;
        const int tg = tid & 15;           // compute mapping
        const int og = tid >> 4;
        const int t0 = tg * 4;
        const int og7 = og & 7;
        // store-pass mapping (2 rows per iter)
        const int lp = tid & 31;
        const int wrow = tid >> 5;
        const int half = lp >> 4;
        const int jj = lp & 15;

        float4 v = __ldg((const float4*)(x + (size_t)n * 1024) + tid);

        for (int b = 0; b < Bq; b++) {
            // ---- stage x row (transposed [c][6+t], stride 84, repl pads) ----
            s_xe[(cq + 0) * XES + 6 + t] = v.x;
            s_xe[(cq + 1) * XES + 6 + t] = v.y;
            s_xe[(cq + 2) * XES + 6 + t] = v.z;
            s_xe[(cq + 3) * XES + 6 + t] = v.w;
            if (t == 0) {
                #pragma unroll
                for (int j = 0; j < 6; j++) {
                    s_xe[(cq + 0) * XES + j] = v.x;
                    s_xe[(cq + 1) * XES + j] = v.y;
                    s_xe[(cq + 2) * XES + j] = v.z;
                    s_xe[(cq + 3) * XES + j] = v.w;
                }
            }
            if (t == 63) {
                #pragma unroll
                for (int j = 70; j < 80; j++) {
                    s_xe[(cq + 0) * XES + j] = v.x;
                    s_xe[(cq + 1) * XES + j] = v.y;
                    s_xe[(cq + 2) * XES + j] = v.z;
                    s_xe[(cq + 3) * XES + j] = v.w;
                }
            }
            __syncthreads();
            if (b + 1 < Bq)
                v = __ldg((const float4*)(x + (size_t)((b + 1) * Nn + n) * 1024) + tid);

            if (og < 8) {
                // ---- group A: ks=12 branch, logical pairs j = 24+og7 ----
                u64 ia = *(const u64*)&s_btc[48 + og7 * 2];
                u64 acc[4] = {ia, ia, ia, ia};
                #pragma unroll
                for (int c = 0; c < 16; c++) {
                    const float4* xr = (const float4*)&s_xe[c * XES + t0];
                    float4 x0 = xr[0], x1 = xr[1], x2 = xr[2], x3 = xr[3];
                    u64 xp[15];
                    xp[0] = pk2(x0.x); xp[1] = pk2(x0.y); xp[2] = pk2(x0.z); xp[3] = pk2(x0.w);
                    xp[4] = pk2(x1.x); xp[5] = pk2(x1.y); xp[6] = pk2(x1.z); xp[7] = pk2(x1.w);
                    xp[8] = pk2(x2.x); xp[9] = pk2(x2.y); xp[10] = pk2(x2.z); xp[11] = pk2(x2.w);
                    xp[12] = pk2(x3.x); xp[13] = pk2(x3.y); xp[14] = pk2(x3.z);
                    #pragma unroll
                    for (int p = 0; p < 6; p++) {
                        ulonglong2 w = *(const ulonglong2*)
                            &s_wA[((c * 6 + p) * 8 + og7) * 4];
                        #pragma unroll
                        for (int dt = 0; dt < 4; dt++) {
                            fma2(acc[dt], xp[2 * p + dt], w.x);
                            fma2(acc[dt], xp[2 * p + 1 + dt], w.y);
                        }
                    }
                }
                #pragma unroll
                for (int dt = 0; dt < 4; dt++) {
                    int row = t0 + dt;
                    int swp = ((24 + og7 + 2 * tg) & 31) * 2;
                    *(u64*)&s_out[row * 64 + swp] = acc[dt];
                }
            } else {
                // ---- group B: ks 2/3/6, logical pairs j = br*8+og7 ----
                u64 acc[12];
                #pragma unroll
                for (int br = 0; br < 3; br++) {
                    u64 ib = *(const u64*)&s_btc[br * 16 + og7 * 2];
                    #pragma unroll
                    for (int dt = 0; dt < 4; dt++) acc[br * 4 + dt] = ib;
                }
                #pragma unroll
                for (int c = 0; c < 16; c++) {
                    const float4* xr = (const float4*)&s_xe[c * XES + t0 + 4];
                    float4 x0 = xr[0], x1 = xr[1];
                    float xl8 = s_xe[c * XES + t0 + 12];
                    u64 xp[9];
                    xp[0] = pk2(x0.x); xp[1] = pk2(x0.y); xp[2] = pk2(x0.z); xp[3] = pk2(x0.w);
                    xp[4] = pk2(x1.x); xp[5] = pk2(x1.y); xp[6] = pk2(x1.z); xp[7] = pk2(x1.w);
                    xp[8] = pk2(xl8);
                    const int BRS[6] = {0, 1, 1, 2, 2, 2};
                    const int SL[6] = {2, 1, 3, 0, 2, 4};
                    const int SH[6] = {3, 2, 3, 1, 3, 5};
                    #pragma unroll
                    for (int p = 0; p < 6; p++) {
                        ulonglong2 w = *(const ulonglong2*)
                            &s_wB[((c * 6 + p) * 8 + og7) * 4];
                        const int ab = BRS[p] * 4;
                        #pragma unroll
                        for (int dt = 0; dt < 4; dt++) {
                            fma2(acc[ab + dt], xp[SL[p] + dt], w.x);
                            if (p != 2) fma2(acc[ab + dt], xp[SH[p] + dt], w.y);
                        }
                    }
                }
                #pragma unroll
                for (int br = 0; br < 3; br++)
                    #pragma unroll
                    for (int dt = 0; dt < 4; dt++) {
                        int row = t0 + dt;
                        int swp = ((br * 8 + og7 + 2 * tg) & 31) * 2;
                        *(u64*)&s_out[row * 64 + swp] = acc[br * 4 + dt];
                    }
            }
            __syncthreads();

            // ---- store pass: 2 rows/iter, LDS.128 + STG.128, conflict-free --
            {
                float* op = out + (size_t)(b * Nn + n) * 5120;
                #pragma unroll
                for (int it = 0; it < 4; it++) {
                    int row = it * 16 + wrow * 2 + half;
                    int p = (2 * jj + 2 * (row >> 2)) & 31;
                    float4 d = *(const float4*)&s_out[row * 64 + p * 2];
                    d.x = ftanh(d.x); d.y = ftanh(d.y);
                    d.z = ftanh(d.z); d.w = ftanh(d.w);
                    *(float4*)&op[row * 80 + 4 * jj] = d;
                }
            }
        }
    } else {
        // ==================== SPATIAL ROLE (CSR from k_prep) ================
        float* s_wg = sm;              // 256  [c][o]
        float* s_bg = sm + 256;        // 16
        float* s_bs = sm + 272;        // 64
        float* s_wsT = sm + 336;       // 64*65 [t][s]
        float* s_agg = sm + 4496;      // [16][65]
        float* s_xl = sm + 5536;       // [64][20]
        u64* s_elw = (u64*)(sm + 6816);   // ELCAP packed (dinv*dvn, row)

        const int n = cid;

        for (int i = tid; i < 4096; i += 256) {
            int s0 = i >> 6, tt = i & 63;
            s_wsT[tt * 65 + s0] = w_slin[i];
        }
        {
            int o = tid >> 4, c = tid & 15;
            s_wg[c * 16 + o] = w_gcn[tid];
        }
        if (tid < 64) s_bs[tid] = b_slin[tid];
        if (tid < 16) s_bg[tid] = b_gcn[tid];

        const int lo = g_off[n];
        int cnt = g_off[n + 1] - lo;
        if (cnt > ELCAP) cnt = ELCAP;
        const float dvn = g_dinv[n];
        const float sw = dvn * dvn;
        for (int i = tid; i < cnt; i += 256) {
            int r = __ldg(&g_adj[lo + i]);
            float w = __ldg(&g_dinv[r]) * dvn;
            s_elw[i] = ((u64)__float_as_uint(w) << 32) | (unsigned int)r;
        }
        __syncthreads();

        const int tq = tid >> 2;
        const int cq = (tid & 3) * 4;
        const int t64 = tid & 63, h = tid >> 6;

        float4 a = __ldg((const float4*)(x + (size_t)n * 1024) + tid);

        for (int b = 0; b < Bq; b++) {
            // ---- gather (MLP-4 bursts, sorted-neighbor deterministic order) --
            float a0 = sw * a.x, a1 = sw * a.y, a2 = sw * a.z, a3 = sw * a.w;
            for (int k0 = 0; k0 < cnt; k0 += 4) {
                float4 pv[4];
                float pw[4];
                #pragma unroll
                for (int j = 0; j < 4; j++) {
                    int kk = k0 + j;
                    if (kk < cnt) {
                        u64 e = s_elw[kk];
                        int r = (int)(unsigned int)(e & 0xffffffffu);
                        pw[j] = __uint_as_float((unsigned int)(e >> 32));
                        pv[j] = __ldg((const float4*)(x + (size_t)(b * Nn + r) * 1024) + tid);
                    }
                }
                #pragma unroll
                for (int j = 0; j < 4; j++) {
                    if (k0 + j < cnt) {
                        a0 += pw[j] * pv[j].x; a1 += pw[j] * pv[j].y;
                        a2 += pw[j] * pv[j].z; a3 += pw[j] * pv[j].w;
                    }
                }
            }
            s_agg[(cq + 0) * 65 + tq] = a0;
            s_agg[(cq + 1) * 65 + tq] = a1;
            s_agg[(cq + 2) * 65 + tq] = a2;
            s_agg[(cq + 3) * 65 + tq] = a3;
            // prefetch next-b self row (latency hidden under GCN + slin)
            if (b + 1 < Bq)
                a = __ldg((const float4*)(x + (size_t)((b + 1) * Nn + n) * 1024) + tid);
            __syncthreads();

            // ---- GCN transform (wg via single LDS.128) ----
            {
                u64 tacc0 = *(const u64*)&s_bg[h * 4];
                u64 tacc1 = *(const u64*)&s_bg[h * 4 + 2];
                #pragma unroll
                for (int c = 0; c < 16; c++) {
                    u64 a2d = pk2(s_agg[c * 65 + t64]);
                    ulonglong2 wg2 = *(const ulonglong2*)&s_wg[c * 16 + h * 4];
                    fma2(tacc0, a2d, wg2.x);
                    fma2(tacc1, a2d, wg2.y);
                }
                ulonglong2 tw;
                tw.x = tacc0; tw.y = tacc1;
                *(ulonglong2*)&s_xl[t64 * 20 + h * 4] = tw;
            }
            __syncthreads();

            // ---- slin (xl via single LDS.128) + tanh + store cols 64..79 ----
            {
                u64 sb = pk2(s_bs[t64]);
                u64 sa0 = sb, sa1 = sb;
                #pragma unroll 4
                for (int tt = 0; tt < 64; tt++) {
                    u64 w2 = pk2(s_wsT[tt * 65 + t64]);
                    ulonglong2 xl2 = *(const ulonglong2*)&s_xl[tt * 20 + h * 4];
                    fma2(sa0, xl2.x, w2);
                    fma2(sa1, xl2.y, w2);
                }
                float2 r0 = tanh2(sa0);
                float2 r1 = tanh2(sa1);
                float4 o4 = {r0.x, r0.y, r1.x, r1.y};
                float* op = out + ((size_t)(b * Nn + n) * 64 + t64) * 80 + 64 + h * 4;
                *(float4*)op = o4;
            }
        }
    }
}

// ---------------- launch ------------------------------------------------------
extern "C" void kernel_launch(void* const* d_in, const int* in_sizes, int n_in,
                              void* d_out, int out_size) {
    const float* x = (const float*)d_in[0];
    const int* ei = (const int*)d_in[1];
    const float* w_t2 = (const float*)d_in[2];
    const float* b_t2 = (const float*)d_in[3];
    const float* w_t3 = (const float*)d_in[4];
    const float* b_t3 = (const float*)d_in[5];
    const float* w_t6 = (const float*)d_in[6];
    const float* b_t6 = (const float*)d_in[7];
    const float* w_t12 = (const float*)d_in[8];
    const float* b_t12 = (const float*)d_in[9];
    const float* w_gcn = (const float*)d_in[10];
    const float* b_gcn = (const float*)d_in[11];
    const float* w_slin = (const float*)d_in[12];
    const float* b_slin = (const float*)d_in[13];
    float* out = (float*)d_out;

    k_prep<<<1, 1024>>>(ei);
    k_work<<<2048, 256>>>(x, ei, w_t2, b_t2, w_t3, b_t3, w_t6, b_t6,
                          w_t12, b_t12, w_gcn, b_gcn, w_slin, b_slin, out);
}

// round 16
// speedup vs baseline: 1.1972x; 1.1972x over previous
#include <cuda_runtime.h>
#include <math.h>

#define Bq 8
#define Nn 1024
#define Ee 16384
#define ELCAP 192

typedef unsigned long long u64;

__device__ float g_dinv[Nn];

__device__ __forceinline__ u64 pk2(float x) {
    unsigned int xi = __float_as_uint(x);
    u64 r;
    asm("mov.b64 %0, {%1, %1};" : "=l"(r) : "r"(xi));
    return r;
}
__device__ __forceinline__ void fma2(u64& d, u64 a, u64 b) {
    asm("fma.rn.f32x2 %0, %1, %2, %3;" : "=l"(d) : "l"(a), "l"(b), "l"(d));
}
__device__ __forceinline__ float ftanh(float v) {
    float r;
    asm("tanh.approx.f32 %0, %1;" : "=f"(r) : "f"(v));
    return r;
}
__device__ __forceinline__ float2 tanh2(u64 a) {
    unsigned int lo, hi;
    asm("mov.b64 {%0, %1}, %2;" : "=r"(lo), "=r"(hi) : "l"(a));
    float2 r;
    r.x = ftanh(__uint_as_float(lo));
    r.y = ftanh(__uint_as_float(hi));
    return r;
}

// ---- tiny prep: degree histogram -> g_dinv (one CTA) ------------------------
__global__ void k_deg(const int* __restrict__ ei) {
    __shared__ int sdeg[Nn];
    const int tid = threadIdx.x;
    sdeg[tid] = 0;
    __syncthreads();
    const int* colp = ei + Ee;
    for (int e = tid; e < Ee; e += 1024) atomicAdd(&sdeg[colp[e]], 1);
    __syncthreads();
    g_dinv[tid] = rsqrtf((float)sdeg[tid] + 1.0f);
}

#define XES 84
#define SMEM_FLOATS 11648

// grid = 2048, 256 threads. bid&1: 0 -> conv role (all 8 b), 1 -> spatial role.
__global__ void __launch_bounds__(256, 3)
k_work(const float* __restrict__ x, const int* __restrict__ ei,
       const float* __restrict__ w_t2, const float* __restrict__ b_t2,
       const float* __restrict__ w_t3, const float* __restrict__ b_t3,
       const float* __restrict__ w_t6, const float* __restrict__ b_t6,
       const float* __restrict__ w_t12, const float* __restrict__ b_t12,
       const float* __restrict__ w_gcn, const float* __restrict__ b_gcn,
       const float* __restrict__ w_slin, const float* __restrict__ b_slin,
       float* __restrict__ out) {
    __shared__ __align__(16) float sm[SMEM_FLOATS];
    const int bid = blockIdx.x;
    const int tid = threadIdx.x;
    const int cid = bid >> 1;
    const int role = bid & 1;

    if (role == 0) {
        // ==================== CONV ROLE (R14-validated, unchanged) ==========
        float* s_wA = sm;             // 3072
        float* s_wB = sm + 3072;      // 3072
        float* s_btc = sm + 6144;     // 64
        float* s_xe = sm + 6208;      // 16*84
        float* s_out = sm + 7552;     // 64*64 pair-swizzled

        const int n = cid;

        // Paired weight tables (validated layout):
        //  A (ks12): pairs p=0..5 -> taps (2p,2p+1)
        //  B: p0 br0 (sft 6,7); p1 br1 (5,6); p2 br1 (7, ZERO);
        //     p3 br2 (4,5); p4 br2 (6,7); p5 br2 (8,9)
        //  entry [(lo,oc0),(lo,oc1),(hi,oc0),(hi,oc1)] at ((c*6+p)*8+ocp)*4
        for (int i = tid; i < 6144; i += 256) {
            int il = (i < 3072) ? i : (i - 3072);
            int c = il / 192;
            int r = il - c * 192;
            int p = r >> 5;
            int ocp = (r >> 2) & 7;
            int qq = r & 3;
            int kh = qq >> 1;
            int oc = ocp * 2 + (qq & 1);
            float v;
            if (i < 3072) {
                v = w_t12[(oc * 16 + c) * 12 + 2 * p + kh];
            } else {
                if (p == 0)      v = w_t2[(oc * 16 + c) * 2 + kh];
                else if (p == 1) v = w_t3[(oc * 16 + c) * 3 + kh];
                else if (p == 2) v = kh ? 0.0f : w_t3[(oc * 16 + c) * 3 + 2];
                else             v = w_t6[(oc * 16 + c) * 6 + (p - 3) * 2 + kh];
            }
            sm[i] = v;
        }
        if (tid < 64) {
            s_btc[tid] = (tid < 16) ? b_t2[tid]
                       : (tid < 32) ? b_t3[tid - 16]
                       : (tid < 48) ? b_t6[tid - 32]
                                    : b_t12[tid - 48];
        }

        const int t = tid >> 2;            // loader mapping
        const int cq = (tid & 3) * 4;
        const int tg = tid & 15;           // compute mapping
        const int og = tid >> 4;
        const int t0 = tg * 4;
        const int og7 = og & 7;
        // store-pass mapping (2 rows per iter)
        const int lp = tid & 31;
        const int wrow = tid >> 5;
        const int half = lp >> 4;
        const int jj = lp & 15;

        float4 v = __ldg((const float4*)(x + (size_t)n * 1024) + tid);

        for (int b = 0; b < Bq; b++) {
            // ---- stage x row (transposed [c][6+t], stride 84, repl pads) ----
            s_xe[(cq + 0) * XES + 6 + t] = v.x;
            s_xe[(cq + 1) * XES + 6 + t] = v.y;
            s_xe[(cq + 2) * XES + 6 + t] = v.z;
            s_xe[(cq + 3) * XES + 6 + t] = v.w;
            if (t == 0) {
                #pragma unroll
                for (int j = 0; j < 6; j++) {
                    s_xe[(cq + 0) * XES + j] = v.x;
                    s_xe[(cq + 1) * XES + j] = v.y;
                    s_xe[(cq + 2) * XES + j] = v.z;
                    s_xe[(cq + 3) * XES + j] = v.w;
                }
            }
            if (t == 63) {
                #pragma unroll
                for (int j = 70; j < 80; j++) {
                    s_xe[(cq + 0) * XES + j] = v.x;
                    s_xe[(cq + 1) * XES + j] = v.y;
                    s_xe[(cq + 2) * XES + j] = v.z;
                    s_xe[(cq + 3) * XES + j] = v.w;
                }
            }
            __syncthreads();
            if (b + 1 < Bq)
                v = __ldg((const float4*)(x + (size_t)((b + 1) * Nn + n) * 1024) + tid);

            if (og < 8) {
                // ---- group A: ks=12 branch, logical pairs j = 24+og7 ----
                u64 ia = *(const u64*)&s_btc[48 + og7 * 2];
                u64 acc[4] = {ia, ia, ia, ia};
                #pragma unroll
                for (int c = 0; c < 16; c++) {
                    const float4* xr = (const float4*)&s_xe[c * XES + t0];
                    float4 x0 = xr[0], x1 = xr[1], x2 = xr[2], x3 = xr[3];
                    u64 xp[15];
                    xp[0] = pk2(x0.x); xp[1] = pk2(x0.y); xp[2] = pk2(x0.z); xp[3] = pk2(x0.w);
                    xp[4] = pk2(x1.x); xp[5] = pk2(x1.y); xp[6] = pk2(x1.z); xp[7] = pk2(x1.w);
                    xp[8] = pk2(x2.x); xp[9] = pk2(x2.y); xp[10] = pk2(x2.z); xp[11] = pk2(x2.w);
                    xp[12] = pk2(x3.x); xp[13] = pk2(x3.y); xp[14] = pk2(x3.z);
                    #pragma unroll
                    for (int p = 0; p < 6; p++) {
                        ulonglong2 w = *(const ulonglong2*)
                            &s_wA[((c * 6 + p) * 8 + og7) * 4];
                        #pragma unroll
                        for (int dt = 0; dt < 4; dt++) {
                            fma2(acc[dt], xp[2 * p + dt], w.x);
                            fma2(acc[dt], xp[2 * p + 1 + dt], w.y);
                        }
                    }
                }
                #pragma unroll
                for (int dt = 0; dt < 4; dt++) {
                    int row = t0 + dt;
                    int swp = ((24 + og7 + 2 * tg) & 31) * 2;
                    *(u64*)&s_out[row * 64 + swp] = acc[dt];
                }
            } else {
                // ---- group B: ks 2/3/6, logical pairs j = br*8+og7 ----
                u64 acc[12];
                #pragma unroll
                for (int br = 0; br < 3; br++) {
                    u64 ib = *(const u64*)&s_btc[br * 16 + og7 * 2];
                    #pragma unroll
                    for (int dt = 0; dt < 4; dt++) acc[br * 4 + dt] = ib;
                }
                #pragma unroll
                for (int c = 0; c < 16; c++) {
                    const float4* xr = (const float4*)&s_xe[c * XES + t0 + 4];
                    float4 x0 = xr[0], x1 = xr[1];
                    float xl8 = s_xe[c * XES + t0 + 12];
                    u64 xp[9];
                    xp[0] = pk2(x0.x); xp[1] = pk2(x0.y); xp[2] = pk2(x0.z); xp[3] = pk2(x0.w);
                    xp[4] = pk2(x1.x); xp[5] = pk2(x1.y); xp[6] = pk2(x1.z); xp[7] = pk2(x1.w);
                    xp[8] = pk2(xl8);
                    const int BRS[6] = {0, 1, 1, 2, 2, 2};
                    const int SL[6] = {2, 1, 3, 0, 2, 4};
                    const int SH[6] = {3, 2, 3, 1, 3, 5};
                    #pragma unroll
                    for (int p = 0; p < 6; p++) {
                        ulonglong2 w = *(const ulonglong2*)
                            &s_wB[((c * 6 + p) * 8 + og7) * 4];
                        const int ab = BRS[p] * 4;
                        #pragma unroll
                        for (int dt = 0; dt < 4; dt++) {
                            fma2(acc[ab + dt], xp[SL[p] + dt], w.x);
                            if (p != 2) fma2(acc[ab + dt], xp[SH[p] + dt], w.y);
                        }
                    }
                }
                #pragma unroll
                for (int br = 0; br < 3; br++)
                    #pragma unroll
                    for (int dt = 0; dt < 4; dt++) {
                        int row = t0 + dt;
                        int swp = ((br * 8 + og7 + 2 * tg) & 31) * 2;
                        *(u64*)&s_out[row * 64 + swp] = acc[br * 4 + dt];
                    }
            }
            __syncthreads();

            // ---- store pass: 2 rows/iter, LDS.128 + STG.128, conflict-free --
            {
                float* op = out + (size_t)(b * Nn + n) * 5120;
                #pragma unroll
                for (int it = 0; it < 4; it++) {
                    int row = it * 16 + wrow * 2 + half;
                    int p = (2 * jj + 2 * (row >> 2)) & 31;
                    float4 d = *(const float4*)&s_out[row * 64 + p * 2];
                    d.x = ftanh(d.x); d.y = ftanh(d.y);
                    d.z = ftanh(d.z); d.w = ftanh(d.w);
                    *(float4*)&op[row * 80 + 4 * jj] = d;
                }
            }
        }
    } else {
        // ==================== SPATIAL ROLE ==================================
        float* s_wg = sm;              // 256  [c][o]
        float* s_bg = sm + 256;        // 16
        float* s_bs = sm + 272;        // 64
        float* s_wsT = sm + 336;       // 64*65 [t][s]
        float* s_agg = sm + 4496;      // [16][65]
        float* s_xl = sm + 5536;       // [64][20]
        int* s_el = (int*)(sm + 6816);    // ELCAP ints
        u64* s_elw = (u64*)(sm + 7008);   // ELCAP packed (dinv*dvn, row)
        int* s_scan = (int*)(sm + 7392);  // 256

        const int n = cid;

        for (int i = tid; i < 4096; i += 256) {
            int s0 = i >> 6, tt = i & 63;
            s_wsT[tt * 65 + s0] = w_slin[i];
        }
        {
            int o = tid >> 4, c = tid & 15;
            s_wg[c * 16 + o] = w_gcn[tid];
        }
        if (tid < 64) s_bs[tid] = b_slin[tid];
        if (tid < 16) s_bg[tid] = b_gcn[tid];

        // ---- build own edge list (deterministic edge-id order) -------------
        // count pass records a 64-bit match mask; refill iterates set bits only
        const int* colp = ei + Ee;
        const int j0 = tid * 64;
        u64 mask = 0;
        for (int k = 0; k < 64; k += 4) {
            int4 cc = __ldg((const int4*)(colp + j0 + k));
            u64 mb = 0;
            mb |= (cc.x == n) ? 1ULL : 0ULL;
            mb |= (cc.y == n) ? 2ULL : 0ULL;
            mb |= (cc.z == n) ? 4ULL : 0ULL;
            mb |= (cc.w == n) ? 8ULL : 0ULL;
            mask |= mb << k;
        }
        const int m = __popcll(mask);
        s_scan[tid] = m;
        __syncthreads();
        for (int d = 1; d < 256; d <<= 1) {
            int vv = (tid >= d) ? s_scan[tid - d] : 0;
            __syncthreads();
            s_scan[tid] += vv;
            __syncthreads();
        }
        const int base = s_scan[tid] - m;
        const int cnt0 = s_scan[255];
        {
            u64 mm = mask;
            int w = 0;
            while (mm) {
                int k = __ffsll((long long)mm) - 1;
                mm &= mm - 1;
                int pos = base + w;
                if (pos < ELCAP) s_el[pos] = __ldg(&ei[j0 + k]);
                w++;
            }
        }
        __syncthreads();
        const int cnt = (cnt0 < ELCAP) ? cnt0 : ELCAP;
        const float dvn = g_dinv[n];
        const float sw = dvn * dvn;
        for (int i = tid; i < cnt; i += 256) {
            int r = s_el[i];
            float w = g_dinv[r] * dvn;
            s_elw[i] = ((u64)__float_as_uint(w) << 32) | (unsigned int)r;
        }
        __syncthreads();

        const int tq = tid >> 2;
        const int cq = (tid & 3) * 4;
        const int t64 = tid & 63, h = tid >> 6;

        float4 a = __ldg((const float4*)(x + (size_t)n * 1024) + tid);

        for (int b = 0; b < Bq; b++) {
            // ---- gather (MLP-4 bursts, deterministic edge-id order) ----
            float a0 = sw * a.x, a1 = sw * a.y, a2 = sw * a.z, a3 = sw * a.w;
            for (int k0 = 0; k0 < cnt; k0 += 4) {
                float4 pv[4];
                float pw[4];
                #pragma unroll
                for (int j = 0; j < 4; j++) {
                    int kk = k0 + j;
                    if (kk < cnt) {
                        u64 e = s_elw[kk];
                        int r = (int)(unsigned int)(e & 0xffffffffu);
                        pw[j] = __uint_as_float((unsigned int)(e >> 32));
                        pv[j] = __ldg((const float4*)(x + (size_t)(b * Nn + r) * 1024) + tid);
                    }
                }
                #pragma unroll
                for (int j = 0; j < 4; j++) {
                    if (k0 + j < cnt) {
                        a0 += pw[j] * pv[j].x; a1 += pw[j] * pv[j].y;
                        a2 += pw[j] * pv[j].z; a3 += pw[j] * pv[j].w;
                    }
                }
            }
            s_agg[(cq + 0) * 65 + tq] = a0;
            s_agg[(cq + 1) * 65 + tq] = a1;
            s_agg[(cq + 2) * 65 + tq] = a2;
            s_agg[(cq + 3) * 65 + tq] = a3;
            // prefetch next-b self row (latency hidden under GCN + slin)
            if (b + 1 < Bq)
                a = __ldg((const float4*)(x + (size_t)((b + 1) * Nn + n) * 1024) + tid);
            __syncthreads();

            // ---- GCN transform (wg via single LDS.128) ----
            {
                u64 tacc0 = *(const u64*)&s_bg[h * 4];
                u64 tacc1 = *(const u64*)&s_bg[h * 4 + 2];
                #pragma unroll
                for (int c = 0; c < 16; c++) {
                    u64 a2d = pk2(s_agg[c * 65 + t64]);
                    ulonglong2 wg2 = *(const ulonglong2*)&s_wg[c * 16 + h * 4];
                    fma2(tacc0, a2d, wg2.x);
                    fma2(tacc1, a2d, wg2.y);
                }
                ulonglong2 tw;
                tw.x = tacc0; tw.y = tacc1;
                *(ulonglong2*)&s_xl[t64 * 20 + h * 4] = tw;
            }
            __syncthreads();

            // ---- slin (xl via single LDS.128) + tanh + store cols 64..79 ----
            {
                u64 sb = pk2(s_bs[t64]);
                u64 sa0 = sb, sa1 = sb;
                #pragma unroll 4
                for (int tt = 0; tt < 64; tt++) {
                    u64 w2 = pk2(s_wsT[tt * 65 + t64]);
                    ulonglong2 xl2 = *(const ulonglong2*)&s_xl[tt * 20 + h * 4];
                    fma2(sa0, xl2.x, w2);
                    fma2(sa1, xl2.y, w2);
                }
                float2 r0 = tanh2(sa0);
                float2 r1 = tanh2(sa1);
                float4 o4 = {r0.x, r0.y, r1.x, r1.y};
                float* op = out + ((size_t)(b * Nn + n) * 64 + t64) * 80 + 64 + h * 4;
                *(float4*)op = o4;
            }
        }
    }
}

// ---------------- launch ------------------------------------------------------
extern "C" void kernel_launch(void* const* d_in, const int* in_sizes, int n_in,
                              void* d_out, int out_size) {
    const float* x = (const float*)d_in[0];
    const int* ei = (const int*)d_in[1];
    const float* w_t2 = (const float*)d_in[2];
    const float* b_t2 = (const float*)d_in[3];
    const float* w_t3 = (const float*)d_in[4];
    const float* b_t3 = (const float*)d_in[5];
    const float* w_t6 = (const float*)d_in[6];
    const float* b_t6 = (const float*)d_in[7];
    const float* w_t12 = (const float*)d_in[8];
    const float* b_t12 = (const float*)d_in[9];
    const float* w_gcn = (const float*)d_in[10];
    const float* b_gcn = (const float*)d_in[11];
    const float* w_slin = (const float*)d_in[12];
    const float* b_slin = (const float*)d_in[13];
    float* out = (float*)d_out;

    k_deg<<<1, 1024>>>(ei);
    k_work<<<2048, 256>>>(x, ei, w_t2, b_t2, w_t3, b_t3, w_t6, b_t6,
                          w_t12, b_t12, w_gcn, b_gcn, w_slin, b_slin, out);
}